// round 14
// baseline (speedup 1.0000x reference)
#include <cuda_runtime.h>
#include <cuda_fp16.h>
#include <cstdint>

#define NT 365
#define NB 2048
#define NXD 32
#define HID 256
#define NG 1024
#define TSPLIT 184
#define STAGES 4
#define SA_BYTES 10240                 // A stage: 128 rows * 80B
#define STG_GX (SA_BYTES + 10240)      // + B 128 rows (gemm_gx only)
#define SMEM_GX (STAGES * STG_GX)      // 81920
// persistent step kernel smem: 4 A-stages + resident W (128 x 528B)
#define WROW 528
#define WSLAB (128 * WROW)             // 67584
#define SMEM_PS (STAGES * SA_BYTES + WSLAB)   // 40960 + 67584 = 108544

// ---- device-global scratch (no cudaMalloc allowed) ----
__device__ __half g_x0[(size_t)NT * NB * HID];            // 383 MB
__device__ float g_gx0[(size_t)TSPLIT * NB * NG];         // 1.54 GB
__device__ float g_gx1[(size_t)(NT - TSPLIT) * NB * NG];  // 1.52 GB
__device__ __half g_h[2 * NB * HID];
__device__ __half g_wih[NG * HID];     // permuted [C][k]
__device__ __half g_whh[NG * HID];
__device__ float g_biasQ[NG];          // layout 4j+g
__device__ unsigned g_barG[16];        // per-batch-group monotonic arrival counters
__device__ volatile unsigned g_epochG[16];

// =====================================================================
// baseline-PTX helpers (sm_80-era: ldmatrix / mma.sync / cp.async)
// =====================================================================
__device__ __forceinline__ void ldsm4(uint32_t (&r)[4], uint32_t addr) {
    asm volatile("ldmatrix.sync.aligned.m8n8.x4.shared.b16 {%0,%1,%2,%3}, [%4];"
                 : "=r"(r[0]), "=r"(r[1]), "=r"(r[2]), "=r"(r[3]) : "r"(addr));
}
__device__ __forceinline__ void mma16816(float (&d)[4], const uint32_t (&a)[4],
                                         uint32_t b0, uint32_t b1) {
    asm volatile("mma.sync.aligned.m16n8k16.row.col.f32.f16.f16.f32 "
                 "{%0,%1,%2,%3}, {%4,%5,%6,%7}, {%8,%9}, {%0,%1,%2,%3};"
                 : "+f"(d[0]), "+f"(d[1]), "+f"(d[2]), "+f"(d[3])
                 : "r"(a[0]), "r"(a[1]), "r"(a[2]), "r"(a[3]), "r"(b0), "r"(b1));
}
__device__ __forceinline__ uint32_t smem_u32(const void* p) {
    return (uint32_t)__cvta_generic_to_shared(p);
}
__device__ __forceinline__ void cp16(uint32_t dst, const void* src) {
    asm volatile("cp.async.cg.shared.global [%0], [%1], 16;" :: "r"(dst), "l"(src));
}
__device__ __forceinline__ void prefetchL2(const void* p) {
    asm volatile("prefetch.global.L2 [%0];" :: "l"(p));
}
#define CPCOMMIT() asm volatile("cp.async.commit_group;" ::: "memory")
#define CPWAIT2()  asm volatile("cp.async.wait_group 2;" ::: "memory")

// =====================================================================
// gemm_gx core: 128x128 GEMM, K=256 fp16 single-product,
// cp.async 4-stage pipeline, one sync per chunk. (unchanged)
// =====================================================================
__device__ __forceinline__ void gemm_core_gx(
    float (*acc)[4][4],
    const __half* __restrict__ A, size_t arow0,
    const __half* __restrict__ B, size_t brow0,
    char* sm, int tid)
{
    const int lane = tid & 31, wid = tid >> 5;
    const int wm = wid >> 2, wn = wid & 3;
    const uint32_t sbase = smem_u32(sm);

#pragma unroll
    for (int a = 0; a < 4; ++a)
#pragma unroll
        for (int b = 0; b < 4; ++b)
#pragma unroll
            for (int r = 0; r < 4; ++r) acc[a][b][r] = 0.f;

    auto issue = [&](int stage, int nk) {
        int k0 = nk * 32;
        uint32_t dst = sbase + stage * STG_GX;
#pragma unroll
        for (int i = 0; i < 2; ++i) {
            int id = tid + i * 256;
            int row = id >> 2, seg = id & 3;
            cp16(dst + row * 80 + seg * 16,
                 A + arow0 + (size_t)row * HID + k0 + seg * 8);
        }
#pragma unroll
        for (int i = 0; i < 2; ++i) {
            int id = tid + i * 256;
            int row = id >> 2, seg = id & 3;
            cp16(dst + SA_BYTES + row * 80 + seg * 16,
                 B + brow0 + (size_t)row * HID + k0 + seg * 8);
        }
    };

#pragma unroll
    for (int s = 0; s < STAGES - 1; ++s) { issue(s, s); CPCOMMIT(); }

#pragma unroll 1
    for (int kt = 0; kt < 8; ++kt) {
        CPWAIT2();
        __syncthreads();
        if (kt + STAGES - 1 < 8) issue((kt + STAGES - 1) & (STAGES - 1), kt + STAGES - 1);
        CPCOMMIT();

        uint32_t abase = sbase + (kt & (STAGES - 1)) * STG_GX;
        uint32_t bbase = abase + SA_BYTES;
#pragma unroll
        for (int kk = 0; kk < 2; ++kk) {
            uint32_t af[4][4], bf[2][4];
#pragma unroll
            for (int mi = 0; mi < 4; ++mi)
                ldsm4(af[mi], abase + (wm * 64 + mi * 16 + (lane & 15)) * 80
                                    + kk * 32 + (lane >> 4) * 16);
#pragma unroll
            for (int np = 0; np < 2; ++np)
                ldsm4(bf[np], bbase + (wn * 32 + np * 16 + (lane & 15)) * 80
                                    + kk * 32 + (lane >> 4) * 16);
#pragma unroll
            for (int mi = 0; mi < 4; ++mi)
#pragma unroll
                for (int np = 0; np < 2; ++np) {
                    mma16816(acc[mi][2 * np],     af[mi], bf[np][0], bf[np][2]);
                    mma16816(acc[mi][2 * np + 1], af[mi], bf[np][1], bf[np][3]);
                }
        }
    }
}

// =====================================================================
// init / prep_w / input_proj (unchanged from R12)
// =====================================================================
__global__ void init_kernel(const float* __restrict__ b_out, float* __restrict__ out) {
    int i = blockIdx.x * blockDim.x + threadIdx.x;
    int stride = gridDim.x * blockDim.x;
    __half z = __float2half(0.f);
    for (int k = i; k < 2 * NB * HID; k += stride) g_h[k] = z;
    float b0 = b_out[0];
    for (int k = i; k < NT * NB; k += stride) out[k] = b0;
    if (i < 16) { g_barG[i] = 0; g_epochG[i] = 0; }
}

__global__ void prep_w(const float* __restrict__ w_ih, const float* __restrict__ w_hh,
                       const float* __restrict__ b_ih, const float* __restrict__ b_hh) {
    int C = blockIdx.x, k = threadIdx.x;
    int blk32 = C >> 5, r2 = C & 31, ni = r2 >> 3, p = r2 & 7;
    int j = blk32 * 8 + (ni >> 1) * 4 + (p >> 1);
    int g = ((ni & 1) << 1) | (p & 1);
    int src = g * HID + j;
    g_wih[(size_t)C * HID + k] = __float2half_rn(w_ih[(size_t)src * HID + k]);
    g_whh[(size_t)C * HID + k] = __float2half_rn(w_hh[(size_t)src * HID + k]);
    if (k == 0) g_biasQ[4 * j + g] = b_ih[src] + b_hh[src];
}

__global__ void __launch_bounds__(256) input_proj(const float* __restrict__ x,
                                                  const float* __restrict__ w_in,
                                                  const float* __restrict__ b_in) {
    __shared__ float xs[32][NXD];
    int tid = threadIdx.x;
    size_t row0 = (size_t)blockIdx.x * 32;
    const float* xsrc = x + row0 * NXD;
#pragma unroll
    for (int r = 0; r < 4; ++r) {
        int lin = tid + r * 256;
        xs[lin >> 5][lin & 31] = xsrc[lin];
    }
    float w[NXD];
#pragma unroll
    for (int n = 0; n < NXD; ++n) w[n] = w_in[tid * NXD + n];
    float b = b_in[tid];
    __syncthreads();
    __half* dh = g_x0 + row0 * HID + tid;
#pragma unroll 4
    for (int m = 0; m < 32; ++m) {
        float acc = b;
#pragma unroll
        for (int n = 0; n < NXD; ++n) acc = fmaf(xs[m][n], w[n], acc);
        dh[(size_t)m * HID] = __float2half_rn(fmaxf(acc, 0.f));
    }
}

// =====================================================================
// pre-GEMM: gx[R][4j+g] = x0[R] . w_ihP + biasQ ; tiles 128x128 (unchanged)
// =====================================================================
__global__ void __launch_bounds__(256, 2) gemm_gx() {
    extern __shared__ __align__(16) char sm[];
    int tid = threadIdx.x, lane = tid & 31, wid = tid >> 5;
    int wm = wid >> 2, wn = wid & 3;
    int bx = blockIdx.x;
    size_t row0 = (size_t)blockIdx.y * 128;

    float acc[4][4][4];
    gemm_core_gx(acc, g_x0, row0 * HID, g_wih, (size_t)bx * 128 * HID, sm, tid);

    float* gx; size_t R0;
    if (row0 < (size_t)TSPLIT * NB) { gx = g_gx0; R0 = row0; }
    else { gx = g_gx1; R0 = row0 - (size_t)TSPLIT * NB; }

    int q = lane >> 2;
#pragma unroll
    for (int np = 0; np < 2; ++np) {
        int jl = wn * 8 + np * 4 + (lane & 3);
        float4 bv = *(const float4*)(g_biasQ + bx * 128 + jl * 4);
#pragma unroll
        for (int mi = 0; mi < 4; ++mi) {
            size_t R = R0 + wm * 64 + mi * 16 + q;
#pragma unroll
            for (int hf = 0; hf < 2; ++hf) {
                float4 v;
                v.x = acc[mi][2 * np][2 * hf + 0] + bv.x;
                v.y = acc[mi][2 * np][2 * hf + 1] + bv.y;
                v.z = acc[mi][2 * np + 1][2 * hf + 0] + bv.z;
                v.w = acc[mi][2 * np + 1][2 * hf + 1] + bv.w;
                *(float4*)(gx + (R + hf * 8) * NG + bx * 128 + jl * 4) = v;
            }
        }
    }
}

// =====================================================================
// PERSISTENT recurrent kernel: 128 CTAs (1 per SM, no co-residency
// imbalance). bx = cta>>4 (8 col-tiles of 128 gate-cols), by = cta&15
// (16 batch-tiles of 128 rows). Warp grid 2x4, warp tile 64x32.
// Resident W slab = 128 cols. Barrier group = 8 CTAs sharing `by`.
// gx[t+1] prefetched BEFORE the barrier wait.
// =====================================================================
__global__ void __launch_bounds__(256, 1) lstm_persist(const float* __restrict__ w_out,
                                                       float* __restrict__ out) {
    extern __shared__ __align__(16) char sm[];
    char* wsm = sm + STAGES * SA_BYTES;
    const uint32_t sbase = smem_u32(sm);
    const uint32_t wbase = sbase + STAGES * SA_BYTES;

    int tid = threadIdx.x, lane = tid & 31, wid = tid >> 5;
    int wm = wid >> 2, wn = wid & 3;
    int cta = blockIdx.x;
    int bx = cta >> 4, by = cta & 15;
    int b0 = by * 128;
    int q = lane >> 2, l2 = lane & 3;

    // ---- load resident weight slab (128 cols x 256 k, fp16) ----
    {
        const __half* WH = g_whh + (size_t)bx * 128 * HID;
#pragma unroll
        for (int i = 0; i < 16; ++i) {
            int id = tid + i * 256;
            int row = id >> 5, seg = id & 31;
            *(float4*)(wsm + row * WROW + seg * 16) =
                *(const float4*)(WH + (size_t)row * HID + seg * 8);
        }
    }
    __syncthreads();

    // ---- persistent per-thread state ----
    float creg[16];
#pragma unroll
    for (int i = 0; i < 16; ++i) creg[i] = 0.f;
    float wo[2];
#pragma unroll
    for (int np = 0; np < 2; ++np) wo[np] = w_out[bx * 32 + wn * 8 + np * 4 + l2];

    // prefetch step-0 gx tile
    {
        const float* gx0 = g_gx0;
        int row = tid >> 1, half = tid & 1;
        prefetchL2((const char*)(gx0 + (size_t)(b0 + row) * NG + bx * 128) + half * 256);
        prefetchL2((const char*)(gx0 + (size_t)(b0 + row) * NG + bx * 128) + 128 + half * 256);
    }

#pragma unroll 1
    for (int t = 0; t < NT; ++t) {
        const __half* hin = g_h + (size_t)(t & 1) * NB * HID;
        __half* hout = g_h + (size_t)((t + 1) & 1) * NB * HID;
        const float* gx = (t < TSPLIT) ? (g_gx0 + (size_t)t * NB * NG)
                                       : (g_gx1 + (size_t)(t - TSPLIT) * NB * NG);

        float acc[4][4][4];
#pragma unroll
        for (int a = 0; a < 4; ++a)
#pragma unroll
            for (int b = 0; b < 4; ++b)
#pragma unroll
                for (int r = 0; r < 4; ++r) acc[a][b][r] = 0.f;

        auto issueA = [&](int stage, int nk) {
            int k0 = nk * 32;
            uint32_t dst = sbase + stage * SA_BYTES;
#pragma unroll
            for (int i = 0; i < 2; ++i) {
                int id = tid + i * 256;
                int row = id >> 2, seg = id & 3;
                cp16(dst + row * 80 + seg * 16,
                     hin + (size_t)(b0 + row) * HID + k0 + seg * 8);
            }
        };

#pragma unroll
        for (int s = 0; s < STAGES - 1; ++s) { issueA(s, s); CPCOMMIT(); }

#pragma unroll 1
        for (int kt = 0; kt < 8; ++kt) {
            CPWAIT2();
            __syncthreads();
            if (kt + STAGES - 1 < 8) issueA((kt + STAGES - 1) & (STAGES - 1), kt + STAGES - 1);
            CPCOMMIT();

            uint32_t abase = sbase + (kt & (STAGES - 1)) * SA_BYTES;
            int k0b = kt * 64;
#pragma unroll
            for (int kk = 0; kk < 2; ++kk) {
                uint32_t af[4][4], bf[2][4];
#pragma unroll
                for (int mi = 0; mi < 4; ++mi)
                    ldsm4(af[mi], abase + (wm * 64 + mi * 16 + (lane & 15)) * 80
                                        + kk * 32 + (lane >> 4) * 16);
#pragma unroll
                for (int np = 0; np < 2; ++np)
                    ldsm4(bf[np], wbase + (wn * 32 + np * 16 + (lane & 15)) * WROW
                                     + k0b + kk * 32 + (lane >> 4) * 16);
#pragma unroll
                for (int mi = 0; mi < 4; ++mi)
#pragma unroll
                    for (int np = 0; np < 2; ++np) {
                        mma16816(acc[mi][2 * np],     af[mi], bf[np][0], bf[np][2]);
                        mma16816(acc[mi][2 * np + 1], af[mi], bf[np][1], bf[np][3]);
                    }
            }
        }

        // ---- fused epilogue: gates -> cell update (c in regs) ----
        float osum[4][2];
#pragma unroll
        for (int mi = 0; mi < 4; ++mi) { osum[mi][0] = 0.f; osum[mi][1] = 0.f; }
#pragma unroll
        for (int np = 0; np < 2; ++np) {
            int jl = wn * 8 + np * 4 + l2;
            int j = bx * 32 + jl;
#pragma unroll
            for (int mi = 0; mi < 4; ++mi) {
#pragma unroll
                for (int hf = 0; hf < 2; ++hf) {
                    int b = b0 + wm * 64 + mi * 16 + q + hf * 8;
                    float4 gv = *(const float4*)(gx + (size_t)b * NG + bx * 128 + jl * 4);
                    float gi = acc[mi][2 * np][2 * hf + 0] + gv.x;
                    float gf = acc[mi][2 * np][2 * hf + 1] + gv.y;
                    float gg = acc[mi][2 * np + 1][2 * hf + 0] + gv.z;
                    float go = acc[mi][2 * np + 1][2 * hf + 1] + gv.w;
                    float ii = 1.f / (1.f + __expf(-gi));
                    float ff = 1.f / (1.f + __expf(-gf));
                    float tg = tanhf(gg);
                    float oo = 1.f / (1.f + __expf(-go));
                    int ci = np * 8 + mi * 2 + hf;
                    float cn = ff * creg[ci] + ii * tg;
                    float hn = oo * tanhf(cn);
                    creg[ci] = cn;
                    hout[(size_t)b * HID + j] = __float2half_rn(hn);
                    osum[mi][hf] = fmaf(hn, wo[np], osum[mi][hf]);
                }
            }
        }
#pragma unroll
        for (int mi = 0; mi < 4; ++mi)
#pragma unroll
            for (int hf = 0; hf < 2; ++hf) {
                float v = osum[mi][hf];
                v += __shfl_xor_sync(0xffffffffu, v, 1);
                v += __shfl_xor_sync(0xffffffffu, v, 2);
                if (l2 == 0) {
                    int b = b0 + wm * 64 + mi * 16 + q + hf * 8;
                    atomicAdd(out + (size_t)t * NB + b, v);
                }
            }

        if (t < NT - 1) {
            // prefetch NEXT step's gx tile before waiting (h-independent)
            {
                const float* gxn = (t + 1 < TSPLIT)
                    ? (g_gx0 + (size_t)(t + 1) * NB * NG)
                    : (g_gx1 + (size_t)(t + 1 - TSPLIT) * NB * NG);
                int row = tid >> 1, half = tid & 1;
                const char* base = (const char*)(gxn + (size_t)(b0 + row) * NG + bx * 128);
                prefetchL2(base + half * 256);
                prefetchL2(base + 128 + half * 256);
            }
            // ---- per-group (8 CTA) barrier: h of this batch-tile visible ----
            __syncthreads();
            if (tid == 0) {
                __threadfence();
                unsigned arr = atomicAdd(&g_barG[by], 1u) + 1u;
                if (arr == 8u * (unsigned)(t + 1)) {
                    __threadfence();
                    g_epochG[by] = (unsigned)(t + 1);
                } else {
                    unsigned e;
                    do {
                        __nanosleep(32);
                        asm volatile("ld.acquire.gpu.u32 %0, [%1];"
                                     : "=r"(e) : "l"((const unsigned*)&g_epochG[by]) : "memory");
                    } while (e < (unsigned)(t + 1));
                }
            }
            __syncthreads();
        }
    }
}

// =====================================================================
extern "C" void kernel_launch(void* const* d_in, const int* in_sizes, int n_in,
                              void* d_out, int out_size) {
    const float* x     = (const float*)d_in[0];
    const float* w_in  = (const float*)d_in[1];
    const float* b_in  = (const float*)d_in[2];
    const float* w_ih  = (const float*)d_in[3];
    const float* w_hh  = (const float*)d_in[4];
    const float* b_ih  = (const float*)d_in[5];
    const float* b_hh  = (const float*)d_in[6];
    const float* w_out = (const float*)d_in[7];
    const float* b_out = (const float*)d_in[8];
    float* out = (float*)d_out;

    static bool attr_done = false;
    if (!attr_done) {
        cudaFuncSetAttribute(gemm_gx, cudaFuncAttributeMaxDynamicSharedMemorySize, SMEM_GX);
        cudaFuncSetAttribute(lstm_persist, cudaFuncAttributeMaxDynamicSharedMemorySize, SMEM_PS);
        attr_done = true;
    }

    init_kernel<<<1024, 256>>>(b_out, out);
    prep_w<<<NG, HID>>>(w_ih, w_hh, b_ih, b_hh);
    input_proj<<<(NT * NB) / 32, 256>>>(x, w_in, b_in);
    gemm_gx<<<dim3(8, (NT * NB) / 128), 256, SMEM_GX>>>();
    lstm_persist<<<128, 256, SMEM_PS>>>(w_out, out);
}

// round 16
// speedup vs baseline: 1.2713x; 1.2713x over previous
#include <cuda_runtime.h>
#include <cuda_fp16.h>
#include <cstdint>

#define NT 365
#define NB 2048
#define NXD 32
#define HID 256
#define NG 1024
#define TSPLIT 184
#define STAGES 4
#define SA_BYTES 10240                 // A stage: 128 rows * 80B
#define STG_GX (SA_BYTES + 10240)      // + B 128 rows (gemm_gx only)
#define SMEM_GX (STAGES * STG_GX)      // 81920
// persistent step kernel smem: 4 A-stages + resident W (64 x 528B)
#define WROW 528
#define WSLAB (64 * WROW)              // 33792
#define SMEM_PS (STAGES * SA_BYTES + WSLAB)   // 40960 + 33792 = 74752

// ---- device-global scratch (no cudaMalloc allowed) ----
__device__ __half g_x0[(size_t)NT * NB * HID];            // 383 MB
__device__ float g_gx0[(size_t)TSPLIT * NB * NG];         // 1.54 GB
__device__ float g_gx1[(size_t)(NT - TSPLIT) * NB * NG];  // 1.52 GB
__device__ __half g_h[2 * NB * HID];
__device__ __half g_wih[NG * HID];     // permuted [C][k]
__device__ __half g_whh[NG * HID];
__device__ float g_biasQ[NG];          // layout 4j+g
__device__ unsigned g_barG[16];        // per-batch-group monotonic arrival counters
__device__ volatile unsigned g_epochG[16];

// =====================================================================
// baseline-PTX helpers (sm_80-era: ldmatrix / mma.sync / cp.async)
// =====================================================================
__device__ __forceinline__ void ldsm4(uint32_t (&r)[4], uint32_t addr) {
    asm volatile("ldmatrix.sync.aligned.m8n8.x4.shared.b16 {%0,%1,%2,%3}, [%4];"
                 : "=r"(r[0]), "=r"(r[1]), "=r"(r[2]), "=r"(r[3]) : "r"(addr));
}
__device__ __forceinline__ void mma16816(float (&d)[4], const uint32_t (&a)[4],
                                         uint32_t b0, uint32_t b1) {
    asm volatile("mma.sync.aligned.m16n8k16.row.col.f32.f16.f16.f32 "
                 "{%0,%1,%2,%3}, {%4,%5,%6,%7}, {%8,%9}, {%0,%1,%2,%3};"
                 : "+f"(d[0]), "+f"(d[1]), "+f"(d[2]), "+f"(d[3])
                 : "r"(a[0]), "r"(a[1]), "r"(a[2]), "r"(a[3]), "r"(b0), "r"(b1));
}
__device__ __forceinline__ uint32_t smem_u32(const void* p) {
    return (uint32_t)__cvta_generic_to_shared(p);
}
__device__ __forceinline__ void cp16(uint32_t dst, const void* src) {
    asm volatile("cp.async.cg.shared.global [%0], [%1], 16;" :: "r"(dst), "l"(src));
}
__device__ __forceinline__ void prefetchL2(const void* p) {
    asm volatile("prefetch.global.L2 [%0];" :: "l"(p));
}
#define CPCOMMIT() asm volatile("cp.async.commit_group;" ::: "memory")
#define CPWAIT2()  asm volatile("cp.async.wait_group 2;" ::: "memory")

// fast activations: EX2 + RCP.APPROX (error ~1e-6, negligible vs fp16 floor)
__device__ __forceinline__ float rcp_fast(float x) {
    float y;
    asm("rcp.approx.f32 %0, %1;" : "=f"(y) : "f"(x));
    return y;
}
__device__ __forceinline__ float sigmoid_fast(float x) {
    return rcp_fast(1.f + __expf(-x));
}
__device__ __forceinline__ float tanh_fast(float x) {
    return fmaf(2.f, rcp_fast(1.f + __expf(-2.f * x)), -1.f);
}

// =====================================================================
// gemm_gx core: 128x128 GEMM, K=256 fp16 single-product,
// cp.async 4-stage pipeline, one sync per chunk.
// =====================================================================
__device__ __forceinline__ void gemm_core_gx(
    float (*acc)[4][4],
    const __half* __restrict__ A, size_t arow0,
    const __half* __restrict__ B, size_t brow0,
    char* sm, int tid)
{
    const int lane = tid & 31, wid = tid >> 5;
    const int wm = wid >> 2, wn = wid & 3;
    const uint32_t sbase = smem_u32(sm);

#pragma unroll
    for (int a = 0; a < 4; ++a)
#pragma unroll
        for (int b = 0; b < 4; ++b)
#pragma unroll
            for (int r = 0; r < 4; ++r) acc[a][b][r] = 0.f;

    auto issue = [&](int stage, int nk) {
        int k0 = nk * 32;
        uint32_t dst = sbase + stage * STG_GX;
#pragma unroll
        for (int i = 0; i < 2; ++i) {
            int id = tid + i * 256;
            int row = id >> 2, seg = id & 3;
            cp16(dst + row * 80 + seg * 16,
                 A + arow0 + (size_t)row * HID + k0 + seg * 8);
        }
#pragma unroll
        for (int i = 0; i < 2; ++i) {
            int id = tid + i * 256;
            int row = id >> 2, seg = id & 3;
            cp16(dst + SA_BYTES + row * 80 + seg * 16,
                 B + brow0 + (size_t)row * HID + k0 + seg * 8);
        }
    };

#pragma unroll
    for (int s = 0; s < STAGES - 1; ++s) { issue(s, s); CPCOMMIT(); }

#pragma unroll 1
    for (int kt = 0; kt < 8; ++kt) {
        CPWAIT2();
        __syncthreads();
        if (kt + STAGES - 1 < 8) issue((kt + STAGES - 1) & (STAGES - 1), kt + STAGES - 1);
        CPCOMMIT();

        uint32_t abase = sbase + (kt & (STAGES - 1)) * STG_GX;
        uint32_t bbase = abase + SA_BYTES;
#pragma unroll
        for (int kk = 0; kk < 2; ++kk) {
            uint32_t af[4][4], bf[2][4];
#pragma unroll
            for (int mi = 0; mi < 4; ++mi)
                ldsm4(af[mi], abase + (wm * 64 + mi * 16 + (lane & 15)) * 80
                                    + kk * 32 + (lane >> 4) * 16);
#pragma unroll
            for (int np = 0; np < 2; ++np)
                ldsm4(bf[np], bbase + (wn * 32 + np * 16 + (lane & 15)) * 80
                                    + kk * 32 + (lane >> 4) * 16);
#pragma unroll
            for (int mi = 0; mi < 4; ++mi)
#pragma unroll
                for (int np = 0; np < 2; ++np) {
                    mma16816(acc[mi][2 * np],     af[mi], bf[np][0], bf[np][2]);
                    mma16816(acc[mi][2 * np + 1], af[mi], bf[np][1], bf[np][3]);
                }
        }
    }
}

// =====================================================================
// init / prep_w / input_proj
// =====================================================================
__global__ void init_kernel(const float* __restrict__ b_out, float* __restrict__ out) {
    int i = blockIdx.x * blockDim.x + threadIdx.x;
    int stride = gridDim.x * blockDim.x;
    __half z = __float2half(0.f);
    for (int k = i; k < 2 * NB * HID; k += stride) g_h[k] = z;
    float b0 = b_out[0];
    for (int k = i; k < NT * NB; k += stride) out[k] = b0;
    if (i < 16) { g_barG[i] = 0; g_epochG[i] = 0; }
}

__global__ void prep_w(const float* __restrict__ w_ih, const float* __restrict__ w_hh,
                       const float* __restrict__ b_ih, const float* __restrict__ b_hh) {
    int C = blockIdx.x, k = threadIdx.x;
    int blk32 = C >> 5, r2 = C & 31, ni = r2 >> 3, p = r2 & 7;
    int j = blk32 * 8 + (ni >> 1) * 4 + (p >> 1);
    int g = ((ni & 1) << 1) | (p & 1);
    int src = g * HID + j;
    g_wih[(size_t)C * HID + k] = __float2half_rn(w_ih[(size_t)src * HID + k]);
    g_whh[(size_t)C * HID + k] = __float2half_rn(w_hh[(size_t)src * HID + k]);
    if (k == 0) g_biasQ[4 * j + g] = b_ih[src] + b_hh[src];
}

__global__ void __launch_bounds__(256) input_proj(const float* __restrict__ x,
                                                  const float* __restrict__ w_in,
                                                  const float* __restrict__ b_in) {
    __shared__ float xs[32][NXD];
    int tid = threadIdx.x;
    size_t row0 = (size_t)blockIdx.x * 32;
    const float* xsrc = x + row0 * NXD;
#pragma unroll
    for (int r = 0; r < 4; ++r) {
        int lin = tid + r * 256;
        xs[lin >> 5][lin & 31] = xsrc[lin];
    }
    float w[NXD];
#pragma unroll
    for (int n = 0; n < NXD; ++n) w[n] = w_in[tid * NXD + n];
    float b = b_in[tid];
    __syncthreads();
    __half* dh = g_x0 + row0 * HID + tid;
#pragma unroll 4
    for (int m = 0; m < 32; ++m) {
        float acc = b;
#pragma unroll
        for (int n = 0; n < NXD; ++n) acc = fmaf(xs[m][n], w[n], acc);
        dh[(size_t)m * HID] = __float2half_rn(fmaxf(acc, 0.f));
    }
}

// =====================================================================
// pre-GEMM: gx[R][4j+g] = x0[R] . w_ihP + biasQ ; tiles 128x128
// =====================================================================
__global__ void __launch_bounds__(256, 2) gemm_gx() {
    extern __shared__ __align__(16) char sm[];
    int tid = threadIdx.x, lane = tid & 31, wid = tid >> 5;
    int wm = wid >> 2, wn = wid & 3;
    int bx = blockIdx.x;
    size_t row0 = (size_t)blockIdx.y * 128;

    float acc[4][4][4];
    gemm_core_gx(acc, g_x0, row0 * HID, g_wih, (size_t)bx * 128 * HID, sm, tid);

    float* gx; size_t R0;
    if (row0 < (size_t)TSPLIT * NB) { gx = g_gx0; R0 = row0; }
    else { gx = g_gx1; R0 = row0 - (size_t)TSPLIT * NB; }

    int q = lane >> 2;
#pragma unroll
    for (int np = 0; np < 2; ++np) {
        int jl = wn * 8 + np * 4 + (lane & 3);
        float4 bv = *(const float4*)(g_biasQ + bx * 128 + jl * 4);
#pragma unroll
        for (int mi = 0; mi < 4; ++mi) {
            size_t R = R0 + wm * 64 + mi * 16 + q;
#pragma unroll
            for (int hf = 0; hf < 2; ++hf) {
                float4 v;
                v.x = acc[mi][2 * np][2 * hf + 0] + bv.x;
                v.y = acc[mi][2 * np][2 * hf + 1] + bv.y;
                v.z = acc[mi][2 * np + 1][2 * hf + 0] + bv.z;
                v.w = acc[mi][2 * np + 1][2 * hf + 1] + bv.w;
                *(float4*)(gx + (R + hf * 8) * NG + bx * 128 + jl * 4) = v;
            }
        }
    }
}

// =====================================================================
// PERSISTENT recurrent kernel (R12 structure: 256 CTAs, 128x64 tiles,
// 2 CTAs/SM). bx = cta>>4 (16 col-tiles of 64 gate-cols), by = cta&15
// (16 batch-tiles of 128 rows). Fast activations; gx[t+1] prefetched
// before the barrier wait.
// =====================================================================
__global__ void __launch_bounds__(256, 2) lstm_persist(const float* __restrict__ w_out,
                                                       float* __restrict__ out) {
    extern __shared__ __align__(16) char sm[];
    char* wsm = sm + STAGES * SA_BYTES;
    const uint32_t sbase = smem_u32(sm);
    const uint32_t wbase = sbase + STAGES * SA_BYTES;

    int tid = threadIdx.x, lane = tid & 31, wid = tid >> 5;
    int wm = wid >> 1, wn = wid & 1;
    int cta = blockIdx.x;
    int bx = cta >> 4, by = cta & 15;
    int b0 = by * 128;
    int q = lane >> 2, l2 = lane & 3;

    // ---- load resident weight slab (64 cols x 256 k, fp16) ----
    {
        const __half* WH = g_whh + (size_t)bx * 64 * HID;
#pragma unroll
        for (int i = 0; i < 8; ++i) {
            int id = tid + i * 256;
            int row = id >> 5, seg = id & 31;
            *(float4*)(wsm + row * WROW + seg * 16) =
                *(const float4*)(WH + (size_t)row * HID + seg * 8);
        }
    }
    __syncthreads();

    // ---- persistent per-thread state ----
    float creg[8];
#pragma unroll
    for (int i = 0; i < 8; ++i) creg[i] = 0.f;
    float wo[2];
#pragma unroll
    for (int np = 0; np < 2; ++np) wo[np] = w_out[bx * 16 + wn * 8 + np * 4 + l2];

    // prefetch step-0 gx tile
    {
        int row = tid >> 1, half = tid & 1;
        prefetchL2((const char*)(g_gx0 + (size_t)(b0 + row) * NG + bx * 64) + half * 128);
    }

#pragma unroll 1
    for (int t = 0; t < NT; ++t) {
        const __half* hin = g_h + (size_t)(t & 1) * NB * HID;
        __half* hout = g_h + (size_t)((t + 1) & 1) * NB * HID;
        const float* gx = (t < TSPLIT) ? (g_gx0 + (size_t)t * NB * NG)
                                       : (g_gx1 + (size_t)(t - TSPLIT) * NB * NG);

        float acc[2][4][4];
#pragma unroll
        for (int a = 0; a < 2; ++a)
#pragma unroll
            for (int b = 0; b < 4; ++b)
#pragma unroll
                for (int r = 0; r < 4; ++r) acc[a][b][r] = 0.f;

        auto issueA = [&](int stage, int nk) {
            int k0 = nk * 32;
            uint32_t dst = sbase + stage * SA_BYTES;
#pragma unroll
            for (int i = 0; i < 2; ++i) {
                int id = tid + i * 256;
                int row = id >> 2, seg = id & 3;
                cp16(dst + row * 80 + seg * 16,
                     hin + (size_t)(b0 + row) * HID + k0 + seg * 8);
            }
        };

#pragma unroll
        for (int s = 0; s < STAGES - 1; ++s) { issueA(s, s); CPCOMMIT(); }

#pragma unroll 1
        for (int kt = 0; kt < 8; ++kt) {
            CPWAIT2();
            __syncthreads();
            if (kt + STAGES - 1 < 8) issueA((kt + STAGES - 1) & (STAGES - 1), kt + STAGES - 1);
            CPCOMMIT();

            uint32_t abase = sbase + (kt & (STAGES - 1)) * SA_BYTES;
            int k0b = kt * 64;
#pragma unroll
            for (int kk = 0; kk < 2; ++kk) {
                uint32_t af[2][4], bf[2][4];
#pragma unroll
                for (int mi = 0; mi < 2; ++mi)
                    ldsm4(af[mi], abase + (wm * 32 + mi * 16 + (lane & 15)) * 80
                                        + kk * 32 + (lane >> 4) * 16);
#pragma unroll
                for (int np = 0; np < 2; ++np)
                    ldsm4(bf[np], wbase + (wn * 32 + np * 16 + (lane & 15)) * WROW
                                     + k0b + kk * 32 + (lane >> 4) * 16);
#pragma unroll
                for (int mi = 0; mi < 2; ++mi)
#pragma unroll
                    for (int np = 0; np < 2; ++np) {
                        mma16816(acc[mi][2 * np],     af[mi], bf[np][0], bf[np][2]);
                        mma16816(acc[mi][2 * np + 1], af[mi], bf[np][1], bf[np][3]);
                    }
            }
        }

        // ---- fused epilogue: gates -> cell update (c in regs) ----
        float osum[2][2];
        osum[0][0] = osum[0][1] = osum[1][0] = osum[1][1] = 0.f;
#pragma unroll
        for (int np = 0; np < 2; ++np) {
            int j = bx * 16 + wn * 8 + np * 4 + l2;
#pragma unroll
            for (int mi = 0; mi < 2; ++mi) {
#pragma unroll
                for (int hf = 0; hf < 2; ++hf) {
                    int b = b0 + wm * 32 + mi * 16 + q + hf * 8;
                    float4 gv = *(const float4*)(gx + (size_t)b * NG + j * 4);
                    float gi = acc[mi][2 * np][2 * hf + 0] + gv.x;
                    float gf = acc[mi][2 * np][2 * hf + 1] + gv.y;
                    float gg = acc[mi][2 * np + 1][2 * hf + 0] + gv.z;
                    float go = acc[mi][2 * np + 1][2 * hf + 1] + gv.w;
                    float ii = sigmoid_fast(gi);
                    float ff = sigmoid_fast(gf);
                    float tg = tanh_fast(gg);
                    float oo = sigmoid_fast(go);
                    int ci = np * 4 + mi * 2 + hf;
                    float cn = ff * creg[ci] + ii * tg;
                    float hn = oo * tanh_fast(cn);
                    creg[ci] = cn;
                    hout[(size_t)b * HID + j] = __float2half_rn(hn);
                    osum[mi][hf] = fmaf(hn, wo[np], osum[mi][hf]);
                }
            }
        }
#pragma unroll
        for (int mi = 0; mi < 2; ++mi)
#pragma unroll
            for (int hf = 0; hf < 2; ++hf) {
                float v = osum[mi][hf];
                v += __shfl_xor_sync(0xffffffffu, v, 1);
                v += __shfl_xor_sync(0xffffffffu, v, 2);
                if (l2 == 0) {
                    int b = b0 + wm * 32 + mi * 16 + q + hf * 8;
                    atomicAdd(out + (size_t)t * NB + b, v);
                }
            }

        if (t < NT - 1) {
            // prefetch NEXT step's gx tile before waiting (h-independent)
            {
                const float* gxn = (t + 1 < TSPLIT)
                    ? (g_gx0 + (size_t)(t + 1) * NB * NG)
                    : (g_gx1 + (size_t)(t + 1 - TSPLIT) * NB * NG);
                int row = tid >> 1, half = tid & 1;
                prefetchL2((const char*)(gxn + (size_t)(b0 + row) * NG + bx * 64) + half * 128);
            }
            // ---- per-group (16 CTA) barrier ----
            __syncthreads();
            if (tid == 0) {
                __threadfence();
                unsigned arr = atomicAdd(&g_barG[by], 1u) + 1u;
                if (arr == 16u * (unsigned)(t + 1)) {
                    __threadfence();
                    g_epochG[by] = (unsigned)(t + 1);
                } else {
                    unsigned e;
                    do {
                        __nanosleep(32);
                        asm volatile("ld.acquire.gpu.u32 %0, [%1];"
                                     : "=r"(e) : "l"((const unsigned*)&g_epochG[by]) : "memory");
                    } while (e < (unsigned)(t + 1));
                }
            }
            __syncthreads();
        }
    }
}

// =====================================================================
extern "C" void kernel_launch(void* const* d_in, const int* in_sizes, int n_in,
                              void* d_out, int out_size) {
    const float* x     = (const float*)d_in[0];
    const float* w_in  = (const float*)d_in[1];
    const float* b_in  = (const float*)d_in[2];
    const float* w_ih  = (const float*)d_in[3];
    const float* w_hh  = (const float*)d_in[4];
    const float* b_ih  = (const float*)d_in[5];
    const float* b_hh  = (const float*)d_in[6];
    const float* w_out = (const float*)d_in[7];
    const float* b_out = (const float*)d_in[8];
    float* out = (float*)d_out;

    static bool attr_done = false;
    if (!attr_done) {
        cudaFuncSetAttribute(gemm_gx, cudaFuncAttributeMaxDynamicSharedMemorySize, SMEM_GX);
        cudaFuncSetAttribute(lstm_persist, cudaFuncAttributeMaxDynamicSharedMemorySize, SMEM_PS);
        attr_done = true;
    }

    init_kernel<<<1024, 256>>>(b_out, out);
    prep_w<<<NG, HID>>>(w_ih, w_hh, b_ih, b_hh);
    input_proj<<<(NT * NB) / 32, 256>>>(x, w_in, b_in);
    gemm_gx<<<dim3(8, (NT * NB) / 128), 256, SMEM_GX>>>();
    lstm_persist<<<256, 256, SMEM_PS>>>(w_out, out);
}

// round 17
// speedup vs baseline: 1.5117x; 1.1890x over previous
#include <cuda_runtime.h>
#include <cuda_fp16.h>
#include <cstdint>

#define NT 365
#define NB 2048
#define NXD 32
#define HID 256
#define NG 1024
#define STAGES 4
#define SA_BYTES 10240                 // A stage: 128 rows * 80B
#define STG_GX (SA_BYTES + 10240)      // + B 128 rows (gemm_gx only)
#define SMEM_GX (STAGES * STG_GX)      // 81920
// persistent kernel smem: 4 A-stages + resident W (64 x 528B) + h-stage 4KB
#define WROW 528
#define WSLAB (64 * WROW)              // 33792
#define SMEM_PS (STAGES * SA_BYTES + WSLAB + 4096)   // 78848

// ---- device-global scratch (no cudaMalloc allowed) ----
__device__ __half g_x0[(size_t)NT * NB * HID];    // 383 MB
__device__ __half g_gxh[(size_t)NT * NB * NG];    // 1.53 GB (fp16 gates)
__device__ __half g_h[2 * NB * HID];
__device__ __half g_wih[NG * HID];     // permuted [C][k]
__device__ __half g_whh[NG * HID];
__device__ float g_biasQ[NG];          // layout 4j+g
__device__ unsigned g_barG[16];        // per-batch-group monotonic arrival counters
__device__ volatile unsigned g_epochG[16];

// =====================================================================
// baseline-PTX helpers (sm_80-era: ldmatrix / mma.sync / cp.async)
// =====================================================================
__device__ __forceinline__ void ldsm4(uint32_t (&r)[4], uint32_t addr) {
    asm volatile("ldmatrix.sync.aligned.m8n8.x4.shared.b16 {%0,%1,%2,%3}, [%4];"
                 : "=r"(r[0]), "=r"(r[1]), "=r"(r[2]), "=r"(r[3]) : "r"(addr));
}
__device__ __forceinline__ void mma16816(float (&d)[4], const uint32_t (&a)[4],
                                         uint32_t b0, uint32_t b1) {
    asm volatile("mma.sync.aligned.m16n8k16.row.col.f32.f16.f16.f32 "
                 "{%0,%1,%2,%3}, {%4,%5,%6,%7}, {%8,%9}, {%0,%1,%2,%3};"
                 : "+f"(d[0]), "+f"(d[1]), "+f"(d[2]), "+f"(d[3])
                 : "r"(a[0]), "r"(a[1]), "r"(a[2]), "r"(a[3]), "r"(b0), "r"(b1));
}
__device__ __forceinline__ uint32_t smem_u32(const void* p) {
    return (uint32_t)__cvta_generic_to_shared(p);
}
__device__ __forceinline__ void cp16(uint32_t dst, const void* src) {
    asm volatile("cp.async.cg.shared.global [%0], [%1], 16;" :: "r"(dst), "l"(src));
}
__device__ __forceinline__ void prefetchL2(const void* p) {
    asm volatile("prefetch.global.L2 [%0];" :: "l"(p));
}
#define CPCOMMIT() asm volatile("cp.async.commit_group;" ::: "memory")
#define CPWAIT2()  asm volatile("cp.async.wait_group 2;" ::: "memory")

// fast activations on MUFU tanh unit (baseline PTX tanh.approx.f32, sm_75+)
__device__ __forceinline__ float tanh_fast(float x) {
    float y;
    asm("tanh.approx.f32 %0, %1;" : "=f"(y) : "f"(x));
    return y;
}
__device__ __forceinline__ float sigmoid_fast(float x) {
    return fmaf(0.5f, tanh_fast(0.5f * x), 0.5f);
}

// =====================================================================
// gemm_gx core: 128x128 GEMM, K=256 fp16 single-product,
// cp.async 4-stage pipeline, one sync per chunk.
// =====================================================================
__device__ __forceinline__ void gemm_core_gx(
    float (*acc)[4][4],
    const __half* __restrict__ A, size_t arow0,
    const __half* __restrict__ B, size_t brow0,
    char* sm, int tid)
{
    const int lane = tid & 31, wid = tid >> 5;
    const int wm = wid >> 2, wn = wid & 3;
    const uint32_t sbase = smem_u32(sm);

#pragma unroll
    for (int a = 0; a < 4; ++a)
#pragma unroll
        for (int b = 0; b < 4; ++b)
#pragma unroll
            for (int r = 0; r < 4; ++r) acc[a][b][r] = 0.f;

    auto issue = [&](int stage, int nk) {
        int k0 = nk * 32;
        uint32_t dst = sbase + stage * STG_GX;
#pragma unroll
        for (int i = 0; i < 2; ++i) {
            int id = tid + i * 256;
            int row = id >> 2, seg = id & 3;
            cp16(dst + row * 80 + seg * 16,
                 A + arow0 + (size_t)row * HID + k0 + seg * 8);
        }
#pragma unroll
        for (int i = 0; i < 2; ++i) {
            int id = tid + i * 256;
            int row = id >> 2, seg = id & 3;
            cp16(dst + SA_BYTES + row * 80 + seg * 16,
                 B + brow0 + (size_t)row * HID + k0 + seg * 8);
        }
    };

#pragma unroll
    for (int s = 0; s < STAGES - 1; ++s) { issue(s, s); CPCOMMIT(); }

#pragma unroll 1
    for (int kt = 0; kt < 8; ++kt) {
        CPWAIT2();
        __syncthreads();
        if (kt + STAGES - 1 < 8) issue((kt + STAGES - 1) & (STAGES - 1), kt + STAGES - 1);
        CPCOMMIT();

        uint32_t abase = sbase + (kt & (STAGES - 1)) * STG_GX;
        uint32_t bbase = abase + SA_BYTES;
#pragma unroll
        for (int kk = 0; kk < 2; ++kk) {
            uint32_t af[4][4], bf[2][4];
#pragma unroll
            for (int mi = 0; mi < 4; ++mi)
                ldsm4(af[mi], abase + (wm * 64 + mi * 16 + (lane & 15)) * 80
                                    + kk * 32 + (lane >> 4) * 16);
#pragma unroll
            for (int np = 0; np < 2; ++np)
                ldsm4(bf[np], bbase + (wn * 32 + np * 16 + (lane & 15)) * 80
                                    + kk * 32 + (lane >> 4) * 16);
#pragma unroll
            for (int mi = 0; mi < 4; ++mi)
#pragma unroll
                for (int np = 0; np < 2; ++np) {
                    mma16816(acc[mi][2 * np],     af[mi], bf[np][0], bf[np][2]);
                    mma16816(acc[mi][2 * np + 1], af[mi], bf[np][1], bf[np][3]);
                }
        }
    }
}

// =====================================================================
// init / prep_w / input_proj
// =====================================================================
__global__ void init_kernel(const float* __restrict__ b_out, float* __restrict__ out) {
    int i = blockIdx.x * blockDim.x + threadIdx.x;
    int stride = gridDim.x * blockDim.x;
    __half z = __float2half(0.f);
    for (int k = i; k < 2 * NB * HID; k += stride) g_h[k] = z;
    float b0 = b_out[0];
    for (int k = i; k < NT * NB; k += stride) out[k] = b0;
    if (i < 16) { g_barG[i] = 0; g_epochG[i] = 0; }
}

__global__ void prep_w(const float* __restrict__ w_ih, const float* __restrict__ w_hh,
                       const float* __restrict__ b_ih, const float* __restrict__ b_hh) {
    int C = blockIdx.x, k = threadIdx.x;
    int blk32 = C >> 5, r2 = C & 31, ni = r2 >> 3, p = r2 & 7;
    int j = blk32 * 8 + (ni >> 1) * 4 + (p >> 1);
    int g = ((ni & 1) << 1) | (p & 1);
    int src = g * HID + j;
    g_wih[(size_t)C * HID + k] = __float2half_rn(w_ih[(size_t)src * HID + k]);
    g_whh[(size_t)C * HID + k] = __float2half_rn(w_hh[(size_t)src * HID + k]);
    if (k == 0) g_biasQ[4 * j + g] = b_ih[src] + b_hh[src];
}

__global__ void __launch_bounds__(256) input_proj(const float* __restrict__ x,
                                                  const float* __restrict__ w_in,
                                                  const float* __restrict__ b_in) {
    __shared__ float xs[32][NXD];
    int tid = threadIdx.x;
    size_t row0 = (size_t)blockIdx.x * 32;
    const float* xsrc = x + row0 * NXD;
#pragma unroll
    for (int r = 0; r < 4; ++r) {
        int lin = tid + r * 256;
        xs[lin >> 5][lin & 31] = xsrc[lin];
    }
    float w[NXD];
#pragma unroll
    for (int n = 0; n < NXD; ++n) w[n] = w_in[tid * NXD + n];
    float b = b_in[tid];
    __syncthreads();
    __half* dh = g_x0 + row0 * HID + tid;
#pragma unroll 4
    for (int m = 0; m < 32; ++m) {
        float acc = b;
#pragma unroll
        for (int n = 0; n < NXD; ++n) acc = fmaf(xs[m][n], w[n], acc);
        dh[(size_t)m * HID] = __float2half_rn(fmaxf(acc, 0.f));
    }
}

// =====================================================================
// pre-GEMM: gxh[R][4j+g] = fp16(x0[R] . w_ihP + biasQ) ; tiles 128x128
// =====================================================================
__global__ void __launch_bounds__(256, 2) gemm_gx() {
    extern __shared__ __align__(16) char sm[];
    int tid = threadIdx.x, lane = tid & 31, wid = tid >> 5;
    int wm = wid >> 2, wn = wid & 3;
    int bx = blockIdx.x;
    size_t row0 = (size_t)blockIdx.y * 128;

    float acc[4][4][4];
    gemm_core_gx(acc, g_x0, row0 * HID, g_wih, (size_t)bx * 128 * HID, sm, tid);

    int q = lane >> 2;
#pragma unroll
    for (int np = 0; np < 2; ++np) {
        int jl = wn * 8 + np * 4 + (lane & 3);
        float4 bv = *(const float4*)(g_biasQ + bx * 128 + jl * 4);
#pragma unroll
        for (int mi = 0; mi < 4; ++mi) {
            size_t R = row0 + wm * 64 + mi * 16 + q;
#pragma unroll
            for (int hf = 0; hf < 2; ++hf) {
                __half2 h2a = __floats2half2_rn(acc[mi][2 * np][2 * hf + 0] + bv.x,
                                                acc[mi][2 * np][2 * hf + 1] + bv.y);
                __half2 h2b = __floats2half2_rn(acc[mi][2 * np + 1][2 * hf + 0] + bv.z,
                                                acc[mi][2 * np + 1][2 * hf + 1] + bv.w);
                uint2 v;
                v.x = *(uint32_t*)&h2a;
                v.y = *(uint32_t*)&h2b;
                *(uint2*)(g_gxh + (R + hf * 8) * NG + bx * 128 + jl * 4) = v;
            }
        }
    }
}

// =====================================================================
// PERSISTENT recurrent kernel: 256 CTAs, 128x64 tiles, 2 CTAs/SM.
// bx = cta>>4 (16 col-tiles of 64 gate-cols / 16 units), by = cta&15.
// fp16 gx; tanh.approx activations; smem-staged coalesced h writes;
// gx[t+1] prefetched before the barrier wait.
// =====================================================================
__global__ void __launch_bounds__(256, 2) lstm_persist(const float* __restrict__ w_out,
                                                       float* __restrict__ out) {
    extern __shared__ __align__(16) char sm[];
    char* wsm = sm + STAGES * SA_BYTES;
    __half* hsm = (__half*)(wsm + WSLAB);     // 128 rows x 16 units
    const uint32_t sbase = smem_u32(sm);
    const uint32_t wbase = sbase + STAGES * SA_BYTES;

    int tid = threadIdx.x, lane = tid & 31, wid = tid >> 5;
    int wm = wid >> 1, wn = wid & 1;
    int cta = blockIdx.x;
    int bx = cta >> 4, by = cta & 15;
    int b0 = by * 128;
    int q = lane >> 2, l2 = lane & 3;

    // ---- load resident weight slab (64 cols x 256 k, fp16) ----
    {
        const __half* WH = g_whh + (size_t)bx * 64 * HID;
#pragma unroll
        for (int i = 0; i < 8; ++i) {
            int id = tid + i * 256;
            int row = id >> 5, seg = id & 31;
            *(float4*)(wsm + row * WROW + seg * 16) =
                *(const float4*)(WH + (size_t)row * HID + seg * 8);
        }
    }
    __syncthreads();

    // ---- persistent per-thread state ----
    float creg[8];
#pragma unroll
    for (int i = 0; i < 8; ++i) creg[i] = 0.f;
    float wo[2];
#pragma unroll
    for (int np = 0; np < 2; ++np) wo[np] = w_out[bx * 16 + wn * 8 + np * 4 + l2];

    // prefetch step-0 gx tile (128 rows x 128B fp16)
    if (tid < 128)
        prefetchL2((const char*)(g_gxh + (size_t)(b0 + tid) * NG + bx * 64));

#pragma unroll 1
    for (int t = 0; t < NT; ++t) {
        const __half* hin = g_h + (size_t)(t & 1) * NB * HID;
        __half* hout = g_h + (size_t)((t + 1) & 1) * NB * HID;
        const __half* gx = g_gxh + (size_t)t * NB * NG;

        float acc[2][4][4];
#pragma unroll
        for (int a = 0; a < 2; ++a)
#pragma unroll
            for (int b = 0; b < 4; ++b)
#pragma unroll
                for (int r = 0; r < 4; ++r) acc[a][b][r] = 0.f;

        auto issueA = [&](int stage, int nk) {
            int k0 = nk * 32;
            uint32_t dst = sbase + stage * SA_BYTES;
#pragma unroll
            for (int i = 0; i < 2; ++i) {
                int id = tid + i * 256;
                int row = id >> 2, seg = id & 3;
                cp16(dst + row * 80 + seg * 16,
                     hin + (size_t)(b0 + row) * HID + k0 + seg * 8);
            }
        };

#pragma unroll
        for (int s = 0; s < STAGES - 1; ++s) { issueA(s, s); CPCOMMIT(); }

#pragma unroll 1
        for (int kt = 0; kt < 8; ++kt) {
            CPWAIT2();
            __syncthreads();
            if (kt + STAGES - 1 < 8) issueA((kt + STAGES - 1) & (STAGES - 1), kt + STAGES - 1);
            CPCOMMIT();

            uint32_t abase = sbase + (kt & (STAGES - 1)) * SA_BYTES;
            int k0b = kt * 64;
#pragma unroll
            for (int kk = 0; kk < 2; ++kk) {
                uint32_t af[2][4], bf[2][4];
#pragma unroll
                for (int mi = 0; mi < 2; ++mi)
                    ldsm4(af[mi], abase + (wm * 32 + mi * 16 + (lane & 15)) * 80
                                        + kk * 32 + (lane >> 4) * 16);
#pragma unroll
                for (int np = 0; np < 2; ++np)
                    ldsm4(bf[np], wbase + (wn * 32 + np * 16 + (lane & 15)) * WROW
                                     + k0b + kk * 32 + (lane >> 4) * 16);
#pragma unroll
                for (int mi = 0; mi < 2; ++mi)
#pragma unroll
                    for (int np = 0; np < 2; ++np) {
                        mma16816(acc[mi][2 * np],     af[mi], bf[np][0], bf[np][2]);
                        mma16816(acc[mi][2 * np + 1], af[mi], bf[np][1], bf[np][3]);
                    }
            }
        }

        // ---- fused epilogue: gates -> cell update (c in regs) ----
        float osum[2][2];
        osum[0][0] = osum[0][1] = osum[1][0] = osum[1][1] = 0.f;
#pragma unroll
        for (int np = 0; np < 2; ++np) {
            int jl = wn * 8 + np * 4 + l2;
            int j = bx * 16 + jl;
#pragma unroll
            for (int mi = 0; mi < 2; ++mi) {
#pragma unroll
                for (int hf = 0; hf < 2; ++hf) {
                    int bl = wm * 32 + mi * 16 + q + hf * 8;
                    int b = b0 + bl;
                    uint2 gv2 = *(const uint2*)(gx + (size_t)b * NG + j * 4);
                    float2 gab = __half22float2(*(__half2*)&gv2.x);
                    float2 gcd = __half22float2(*(__half2*)&gv2.y);
                    float gi = acc[mi][2 * np][2 * hf + 0] + gab.x;
                    float gf = acc[mi][2 * np][2 * hf + 1] + gab.y;
                    float gg = acc[mi][2 * np + 1][2 * hf + 0] + gcd.x;
                    float go = acc[mi][2 * np + 1][2 * hf + 1] + gcd.y;
                    float ii = sigmoid_fast(gi);
                    float ff = sigmoid_fast(gf);
                    float tg = tanh_fast(gg);
                    float oo = sigmoid_fast(go);
                    int ci = np * 4 + mi * 2 + hf;
                    float cn = ff * creg[ci] + ii * tg;
                    float hn = oo * tanh_fast(cn);
                    creg[ci] = cn;
                    hsm[bl * 16 + jl] = __float2half_rn(hn);
                    osum[mi][hf] = fmaf(hn, wo[np], osum[mi][hf]);
                }
            }
        }
#pragma unroll
        for (int mi = 0; mi < 2; ++mi)
#pragma unroll
            for (int hf = 0; hf < 2; ++hf) {
                float v = osum[mi][hf];
                v += __shfl_xor_sync(0xffffffffu, v, 1);
                v += __shfl_xor_sync(0xffffffffu, v, 2);
                if (l2 == 0) {
                    int b = b0 + wm * 32 + mi * 16 + q + hf * 8;
                    atomicAdd(out + (size_t)t * NB + b, v);
                }
            }

        // ---- coalesced h write from smem stage ----
        __syncthreads();
        {
            int row = tid >> 1, hh = tid & 1;
            *(uint4*)(hout + (size_t)(b0 + row) * HID + bx * 16 + hh * 8) =
                *(const uint4*)(hsm + row * 16 + hh * 8);
        }

        if (t < NT - 1) {
            // prefetch NEXT step's gx tile before waiting (h-independent)
            if (tid < 128)
                prefetchL2((const char*)(g_gxh + (size_t)(t + 1) * NB * NG
                                         + (size_t)(b0 + tid) * NG + bx * 64));
            // ---- per-group (16 CTA) barrier ----
            __syncthreads();
            if (tid == 0) {
                __threadfence();
                unsigned arr = atomicAdd(&g_barG[by], 1u) + 1u;
                if (arr == 16u * (unsigned)(t + 1)) {
                    __threadfence();
                    g_epochG[by] = (unsigned)(t + 1);
                } else {
                    unsigned e;
                    do {
                        __nanosleep(32);
                        asm volatile("ld.acquire.gpu.u32 %0, [%1];"
                                     : "=r"(e) : "l"((const unsigned*)&g_epochG[by]) : "memory");
                    } while (e < (unsigned)(t + 1));
                }
            }
            __syncthreads();
        }
    }
}

// =====================================================================
extern "C" void kernel_launch(void* const* d_in, const int* in_sizes, int n_in,
                              void* d_out, int out_size) {
    const float* x     = (const float*)d_in[0];
    const float* w_in  = (const float*)d_in[1];
    const float* b_in  = (const float*)d_in[2];
    const float* w_ih  = (const float*)d_in[3];
    const float* w_hh  = (const float*)d_in[4];
    const float* b_ih  = (const float*)d_in[5];
    const float* b_hh  = (const float*)d_in[6];
    const float* w_out = (const float*)d_in[7];
    const float* b_out = (const float*)d_in[8];
    float* out = (float*)d_out;

    static bool attr_done = false;
    if (!attr_done) {
        cudaFuncSetAttribute(gemm_gx, cudaFuncAttributeMaxDynamicSharedMemorySize, SMEM_GX);
        cudaFuncSetAttribute(lstm_persist, cudaFuncAttributeMaxDynamicSharedMemorySize, SMEM_PS);
        attr_done = true;
    }

    init_kernel<<<1024, 256>>>(b_out, out);
    prep_w<<<NG, HID>>>(w_ih, w_hh, b_ih, b_hh);
    input_proj<<<(NT * NB) / 32, 256>>>(x, w_in, b_in);
    gemm_gx<<<dim3(8, (NT * NB) / 128), 256, SMEM_GX>>>();
    lstm_persist<<<256, 256, SMEM_PS>>>(w_out, out);
}